// round 5
// baseline (speedup 1.0000x reference)
#include <cuda_runtime.h>
#include <cstdint>

// Problem constants
#define NLEN   8192
#define LOGN   13
#define MODES  1024
#define BATCH  32
#define CIN    64
#define COUT   64
#define IROWS  (BATCH*CIN)    // 2048 input rows
#define OROWS  (BATCH*COUT)   // 2048 output rows

// -------- scratch (no allocations allowed; use __device__ globals) --------
// cas table extended to [0, 8192]: tab[k] = cas(2*pi*k/8192)
__device__ __align__(32) float g_tab[8200];
__device__ float g_xm[IROWS*MODES];               // [row=b*64+i][m]  (row-major)
__device__ float g_z [OROWS*MODES];               // [row=b*64+o][m]  (row-major)

// GF(2)-linear smem swizzle. k0^=u5^u9, k1^=u6^u10, k2^=u7^u11, k3^=u8, k4^=u8^u12.
__device__ __forceinline__ int swz(int u) {
    int f = ((u >> 5) & 7) ^ ((u >> 9) & 7)
          ^ (((u >> 8) & 1) * 0x18)
          ^ (((u >> 12) & 1) * 0x10);
    return u ^ f;
}
__device__ __forceinline__ int rev9(int t) { return (int)(__brev((unsigned)t) >> 23); }

// Literal cas values
#define RSQ2  0.70710678118654752f
#define C8L   0.92387953251128674f
#define S8L   0.38268343236508977f

// Packed f32x2 helpers (Blackwell)
typedef unsigned long long ull_t;
__device__ __forceinline__ ull_t pack2(float x) {
    ull_t r; asm("mov.b64 %0, {%1, %1};" : "=l"(r) : "f"(x)); return r;
}
__device__ __forceinline__ ull_t fma2(ull_t a, ull_t b, ull_t c) {
    ull_t d; asm("fma.rn.f32x2 %0, %1, %2, %3;" : "=l"(d) : "l"(a), "l"(b), "l"(c));
    return d;
}
__device__ __forceinline__ void unpack2(ull_t v, float& lo, float& hi) {
    asm("mov.b64 {%0, %1}, %2;" : "=f"(lo), "=f"(hi) : "l"(v));
}

// ---------------------------------------------------------------------------
__global__ void init_table_kernel() {
    int t = blockIdx.x * blockDim.x + threadIdx.x;
    if (t <= NLEN) {
        float s, c;
        sincospif((float)t * (1.0f / 4096.0f), &s, &c);
        g_tab[t] = c + s;
    }
}

// -------- Phase A stages 1-4: all twiddles are literals ---------------------
__device__ __forceinline__ void stagesA(float r[16]) {
    #pragma unroll
    for (int e = 0; e < 16; e += 2) {
        float o = r[e + 1]; r[e + 1] = r[e] - o; r[e] += o;
    }
    #pragma unroll
    for (int g = 0; g < 16; g += 4)
        #pragma unroll
        for (int e = g; e < g + 2; e++) {
            float o = r[e + 2]; r[e + 2] = r[e] - o; r[e] += o;
        }
    {
        const float c3[4] = {1.0f, 1.41421356237309515f, 1.0f, 0.0f};
        #pragma unroll
        for (int eb = 0; eb < 4; eb++)
            #pragma unroll
            for (int g = 0; g < 16; g += 8) {
                int e = g + eb;
                float o = c3[eb] * r[e + 4]; r[e + 4] = r[e] - o; r[e] += o;
            }
    }
    {
        const float c4[8] = {1.0f, 1.30656296487637653f, 1.41421356237309515f,
                             1.30656296487637653f, 1.0f, 0.54119610014619701f,
                             0.0f, -0.54119610014619701f};
        #pragma unroll
        for (int e = 0; e < 8; e++) {
            float o = c4[e] * r[e + 8]; r[e + 8] = r[e] - o; r[e] += o;
        }
    }
}

// -------- Phase B stages 5-8: remapped so twiddles are warp-uniform ---------
__device__ __forceinline__ void phaseB(float* sm, float r[16], int t,
                                       const float* __restrict__ tab) {
    const int wid  = t >> 5;
    const int lane = t & 31;
    const int base = (lane << 8) | wid;
    #pragma unroll
    for (int s = 0; s < 16; s++) r[s] = sm[swz(base | (s << 4))];
    {
        float cas = tab[wid << 8];
        #pragma unroll
        for (int s = 0; s < 16; s += 2) {
            float o = cas * r[s + 1]; r[s + 1] = r[s] - o; r[s] += o;
        }
    }
    #pragma unroll
    for (int sb = 0; sb < 2; sb++) {
        float cas = tab[((sb << 4) | wid) << 7];
        #pragma unroll
        for (int g = 0; g < 16; g += 4) {
            int s = g + sb;
            float o = cas * r[s + 2]; r[s + 2] = r[s] - o; r[s] += o;
        }
    }
    #pragma unroll
    for (int sb = 0; sb < 4; sb++) {
        float cas = tab[((sb << 4) | wid) << 6];
        #pragma unroll
        for (int g = 0; g < 16; g += 8) {
            int s = g + sb;
            float o = cas * r[s + 4]; r[s + 4] = r[s] - o; r[s] += o;
        }
    }
    #pragma unroll
    for (int s = 0; s < 8; s++) {
        float cas = tab[((s << 4) | wid) << 5];
        float o = cas * r[s + 8]; r[s + 8] = r[s] - o; r[s] += o;
    }
    #pragma unroll
    for (int s = 0; s < 16; s++) sm[swz(base | (s << 4))] = r[s];
}

// -------- forward: x[row][0..8192) -> xm[row][0..1024) ----------------------
__global__ __launch_bounds__(512, 2) void fht_fwd_kernel(const float* __restrict__ x) {
    __shared__ float sm[NLEN];
    const int row = blockIdx.x;
    const int t = threadIdx.x;
    const float* __restrict__ tab = g_tab;

    {
        const float4* __restrict__ xr4 =
            reinterpret_cast<const float4*>(x + (size_t)row * NLEN);
        const int rt = rev9(t);
        const int REV4[16] = {0,8,4,12, 2,10,6,14, 1,9,5,13, 3,11,7,15};
        #pragma unroll
        for (int q = 0; q < 4; q++) {
            float4 v = xr4[t * 4 + q];
            sm[swz((REV4[4*q+0] << 9) | rt)] = v.x;
            sm[swz((REV4[4*q+1] << 9) | rt)] = v.y;
            sm[swz((REV4[4*q+2] << 9) | rt)] = v.z;
            sm[swz((REV4[4*q+3] << 9) | rt)] = v.w;
        }
    }
    __syncthreads();

    float r[16];

    {
        #pragma unroll
        for (int e = 0; e < 16; e++) r[e] = sm[swz(t * 16 + e)];
        stagesA(r);
        #pragma unroll
        for (int e = 0; e < 16; e++) sm[swz(t * 16 + e)] = r[e];
    }
    __syncthreads();

    phaseB(sm, r, t, tab);
    __syncthreads();

    {
        const int low8 = t & 255;
        const int base = ((t >> 8) << 12) | low8;
        float c9   = tab[low8 << 4];
        float c10p = tab[low8 << 3], c10m = tab[8192 - (low8 << 3)];
        float c11p = tab[low8 << 2], c11m = tab[8192 - (low8 << 2)];
        float c12p = tab[low8 << 1], c12m = tab[8192 - (low8 << 1)];
        #pragma unroll
        for (int s = 0; s < 16; s++) r[s] = sm[swz(base | (s << 8))];
        #pragma unroll
        for (int s = 0; s < 16; s += 2) {
            float o = c9 * r[s + 1]; r[s + 1] = r[s] - o; r[s] += o;
        }
        #pragma unroll
        for (int g = 0; g < 16; g += 4) {
            float o0 = c10p * r[g + 2]; r[g + 2] = r[g]     - o0; r[g]     += o0;
            float o1 = c10m * r[g + 3]; r[g + 3] = r[g + 1] - o1; r[g + 1] += o1;
        }
        {
            const float w11[4] = { c11p, RSQ2 * (c11p + c11m), c11m, RSQ2 * (c11m - c11p) };
            #pragma unroll
            for (int sb = 0; sb < 4; sb++) {
                r[sb]     += w11[sb] * r[sb + 4];
                r[sb + 8] += w11[sb] * r[sb + 12];
            }
        }
        {
            r[0] += c12p * r[8];
            r[1] += (C8L * c12p + S8L * c12m) * r[9];
            r[2] += (RSQ2 * (c12p + c12m))    * r[10];
            r[3] += (S8L * c12p + C8L * c12m) * r[11];
        }
        #pragma unroll
        for (int s = 0; s < 4; s++) sm[swz(base | (s << 8))] = r[s];
    }
    __syncthreads();

    {
        float* __restrict__ xmr = g_xm + (size_t)row * MODES;
        const int m0 = 2 * t;
        float2 tw = *(const float2*)&tab[m0];
        float e0 = sm[swz(m0)],     o0 = sm[swz(m0 + 4096)];
        float e1 = sm[swz(m0 + 1)], o1 = sm[swz(m0 + 1 + 4096)];
        float2 res;
        res.x = e0 + tw.x * o0;
        res.y = e1 + tw.y * o1;
        *(float2*)&xmr[m0] = res;
    }
}

// -------- inverse: z[row][0..1024) zero-padded -> out[row][0..8192)/8192 ----
__global__ __launch_bounds__(512, 2) void fht_inv_kernel(float* __restrict__ out) {
    __shared__ float sm[NLEN];
    const int row = blockIdx.x;
    const int t = threadIdx.x;
    const float* __restrict__ tab = g_tab;
    const float* __restrict__ zr = g_z + (size_t)row * MODES;

    {
        float v0 = zr[t];
        float v1 = zr[t + 512];
        const int ub = rev9(t) << 4;
        const float c4[8] = {1.0f, 1.30656296487637653f, 1.41421356237309515f,
                             1.30656296487637653f, 1.0f, 0.54119610014619701f,
                             0.0f, -0.54119610014619701f};
        #pragma unroll
        for (int e = 0; e < 8; e++) {
            float o = c4[e] * v1;
            sm[swz(ub | e)]       = v0 + o;
            sm[swz(ub | (e + 8))] = v0 - o;
        }
    }
    __syncthreads();

    float r[16];
    phaseB(sm, r, t, tab);
    __syncthreads();

    {
        const int low8 = t & 255;
        const int base = ((t >> 8) << 12) | low8;
        float c9   = tab[low8 << 4];
        float c10p = tab[low8 << 3], c10m = tab[8192 - (low8 << 3)];
        float c11p = tab[low8 << 2], c11m = tab[8192 - (low8 << 2)];
        float c12p = tab[low8 << 1], c12m = tab[8192 - (low8 << 1)];
        #pragma unroll
        for (int s = 0; s < 16; s++) r[s] = sm[swz(base | (s << 8))];
        #pragma unroll
        for (int s = 0; s < 16; s += 2) {
            float o = c9 * r[s + 1]; r[s + 1] = r[s] - o; r[s] += o;
        }
        #pragma unroll
        for (int g = 0; g < 16; g += 4) {
            float o0 = c10p * r[g + 2]; r[g + 2] = r[g]     - o0; r[g]     += o0;
            float o1 = c10m * r[g + 3]; r[g + 3] = r[g + 1] - o1; r[g + 1] += o1;
        }
        {
            const float w11[4] = { c11p, RSQ2 * (c11p + c11m), c11m, RSQ2 * (c11m - c11p) };
            #pragma unroll
            for (int sb = 0; sb < 4; sb++) {
                float o0 = w11[sb] * r[sb + 4];  r[sb + 4]  = r[sb]     - o0; r[sb]     += o0;
                float o1 = w11[sb] * r[sb + 12]; r[sb + 12] = r[sb + 8] - o1; r[sb + 8] += o1;
            }
        }
        {
            const float w12[8] = {
                c12p,
                C8L * c12p + S8L * c12m,
                RSQ2 * (c12p + c12m),
                S8L * c12p + C8L * c12m,
                c12m,
                -S8L * c12p + C8L * c12m,
                RSQ2 * (c12m - c12p),
                -C8L * c12p + S8L * c12m
            };
            #pragma unroll
            for (int s = 0; s < 8; s++) {
                float o = w12[s] * r[s + 8]; r[s + 8] = r[s] - o; r[s] += o;
            }
        }
        #pragma unroll
        for (int s = 0; s < 16; s++) sm[swz(base | (s << 8))] = r[s];
    }
    __syncthreads();

    {
        const float scale = 1.0f / (float)NLEN;
        float* __restrict__ orow = out + (size_t)row * NLEN;
        const int k0 = 8 * t;
        float4 tw0 = *(const float4*)&tab[k0];
        float4 tw1 = *(const float4*)&tab[k0 + 4];
        float tws[8] = {tw0.x, tw0.y, tw0.z, tw0.w, tw1.x, tw1.y, tw1.z, tw1.w};
        float lo[8], hi[8];
        #pragma unroll
        for (int q = 0; q < 8; q++) {
            float e = sm[swz(k0 + q)];
            float o = sm[swz(k0 + q + 4096)];
            float tt = tws[q] * o;
            lo[q] = (e + tt) * scale;
            hi[q] = (e - tt) * scale;
        }
        *(float4*)&orow[k0]            = make_float4(lo[0], lo[1], lo[2], lo[3]);
        *(float4*)&orow[k0 + 4]        = make_float4(lo[4], lo[5], lo[6], lo[7]);
        *(float4*)&orow[k0 + 4096]     = make_float4(hi[0], hi[1], hi[2], hi[3]);
        *(float4*)&orow[k0 + 4100]     = make_float4(hi[4], hi[5], hi[6], hi[7]);
    }
}

// -------- transpose-free mode mixing ----------------------------------------
// Block (j, bc, oh): modes M = [32j, 32j+32) (lane = mode), paired P = 1024-M;
// batches [8bc, 8bc+8), outputs [32oh, 32oh+32).
// A(lane) -> z(m0+lane), B(lane) -> z((1024-m0-lane)&1023).
// Coverage: A over j=0..15 = [0,512); B over j=0..15 = {0} u [513,1024);
// block j=16 writes only mode 512 (lane 0, A only). No duplicate writes
// except mode 0 (same thread, same value).
__global__ __launch_bounds__(512, 1) void mix_kernel(const float* __restrict__ w) {
    __shared__ float sw0[4][32][34];   // [ii][mlane][o]  (pitch 34: 8B-aligned LDS.64, conflict-free)
    __shared__ float sw1[4][32][34];
    __shared__ float sa [4][32][9];    // [ii][mlane][b]  (pitch 9: conflict-free scalar)
    __shared__ float sd [4][32][9];

    const int j  = blockIdx.x;         // 0..16
    const int bc = blockIdx.y;         // 0..3
    const int oh = blockIdx.z;         // 0..1
    const int m0 = 32 * j;
    const int tid = threadIdx.x;
    const int lane = tid & 31;
    const int warp = tid >> 5;
    const int b0 = (warp >> 2) * 2;    // relative batch base within chunk: 0,2,4,6
    const int o0 = (warp & 3) * 8;     // relative output base within half: 0,8,16,24

    const int mM = m0 + lane;
    const int mP = (1024 - mM) & 1023;

    ull_t A[2][4], B[2][4];
    #pragma unroll
    for (int bb = 0; bb < 2; bb++)
        #pragma unroll
        for (int k = 0; k < 4; k++) { A[bb][k] = 0ull; B[bb][k] = 0ull; }

    #pragma unroll 1
    for (int c = 0; c < 16; c++) {
        const int i0 = c * 4;
        // stage weights: rows (ii, o); each warp loads 8 rows (lane = mode)
        for (int rr = warp; rr < 128; rr += 16) {
            int ii = rr >> 5, o = rr & 31;
            const float* wr = w + ((size_t)((i0 + ii) * 64 + oh * 32 + o)) * MODES;
            sw0[ii][lane][o] = wr[mM];
            sw1[ii][lane][o] = wr[mP];
        }
        // stage a/d: rows (ii, b); each warp loads 2 rows
        for (int rr = warp; rr < 32; rr += 16) {
            int ii = rr >> 3, b = rr & 7;
            const float* xr = g_xm + ((size_t)((bc * 8 + b) * 64 + i0 + ii)) * MODES;
            float vm = xr[mM];
            float vp = xr[mP];
            sa[ii][lane][b] = 0.5f * (vm + vp);
            sd[ii][lane][b] = 0.5f * (vm - vp);
        }
        __syncthreads();

        #pragma unroll
        for (int ii = 0; ii < 4; ii++) {
            float a0 = sa[ii][lane][b0],     d0 = sd[ii][lane][b0];
            float a1 = sa[ii][lane][b0 + 1], d1 = sd[ii][lane][b0 + 1];
            ull_t aa0 = pack2(a0), dd0 = pack2(d0), nd0 = pack2(-d0);
            ull_t aa1 = pack2(a1), dd1 = pack2(d1), nd1 = pack2(-d1);
            #pragma unroll
            for (int k = 0; k < 4; k++) {
                ull_t w0k = *(const ull_t*)&sw0[ii][lane][o0 + 2 * k];
                ull_t w1k = *(const ull_t*)&sw1[ii][lane][o0 + 2 * k];
                A[0][k] = fma2(aa0, w0k, A[0][k]);
                A[0][k] = fma2(dd0, w1k, A[0][k]);
                B[0][k] = fma2(aa0, w1k, B[0][k]);
                B[0][k] = fma2(nd0, w0k, B[0][k]);
                A[1][k] = fma2(aa1, w0k, A[1][k]);
                A[1][k] = fma2(dd1, w1k, A[1][k]);
                B[1][k] = fma2(aa1, w1k, B[1][k]);
                B[1][k] = fma2(nd1, w0k, B[1][k]);
            }
        }
        __syncthreads();
    }

    const bool special = (j == 16);
    #pragma unroll
    for (int bb = 0; bb < 2; bb++) {
        int browbase = (bc * 8 + b0 + bb) * 64 + oh * 32 + o0;
        #pragma unroll
        for (int k = 0; k < 4; k++) {
            float lo, hi, plo, phi_;
            unpack2(A[bb][k], lo, hi);
            unpack2(B[bb][k], plo, phi_);
            size_t r0 = (size_t)(browbase + 2 * k) * MODES;
            size_t r1 = (size_t)(browbase + 2 * k + 1) * MODES;
            if (!special) {
                g_z[r0 + mM] = lo;
                g_z[r1 + mM] = hi;
                g_z[r0 + mP] = plo;
                g_z[r1 + mP] = phi_;
            } else if (lane == 0) {
                g_z[r0 + mM] = lo;    // mode 512 only
                g_z[r1 + mM] = hi;
            }
        }
    }
}

// ---------------------------------------------------------------------------
extern "C" void kernel_launch(void* const* d_in, const int* in_sizes, int n_in,
                              void* d_out, int out_size) {
    const float* x = (const float*)d_in[0];   // [32][64][8192]
    const float* w = (const float*)d_in[1];   // [64][64][1024]
    float* out = (float*)d_out;               // [32][64][8192]

    init_table_kernel<<<(NLEN + 512) / 512, 512>>>();

    fht_fwd_kernel<<<IROWS, 512>>>(x);

    mix_kernel<<<dim3(17, 4, 2), 512>>>(w);

    fht_inv_kernel<<<OROWS, 512>>>(out);
}

// round 6
// speedup vs baseline: 1.1461x; 1.1461x over previous
#include <cuda_runtime.h>
#include <cstdint>

// Problem constants
#define NLEN   8192
#define LOGN   13
#define MODES  1024
#define BATCH  32
#define CIN    64
#define COUT   64
#define IROWS  (BATCH*CIN)    // 2048 input rows
#define OROWS  (BATCH*COUT)   // 2048 output rows

// -------- scratch (no allocations allowed; use __device__ globals) --------
// cas table extended to [0, 8192]: tab[k] = cas(2*pi*k/8192)
__device__ __align__(32) float g_tab[8200];
__device__ float g_xm  [IROWS*MODES];             // [row=b*64+i][m]
__device__ float g_xmT [MODES*IROWS];             // [m][row]
__device__ float g_wT  [MODES*CIN*COUT];          // [m][i*64+o]
__device__ float g_zT  [MODES*OROWS];             // [m][b*64+o]
__device__ float g_z   [OROWS*MODES];             // [row=b*64+o][m]

// GF(2)-linear smem swizzle. k0^=u5^u9, k1^=u6^u10, k2^=u7^u11, k3^=u8, k4^=u8^u12.
__device__ __forceinline__ int swz(int u) {
    int f = ((u >> 5) & 7) ^ ((u >> 9) & 7)
          ^ (((u >> 8) & 1) * 0x18)
          ^ (((u >> 12) & 1) * 0x10);
    return u ^ f;
}
__device__ __forceinline__ int rev9(int t) { return (int)(__brev((unsigned)t) >> 23); }

// Literal cas values
#define RSQ2  0.70710678118654752f
#define C8L   0.92387953251128674f
#define S8L   0.38268343236508977f

// Packed f32x2 helpers (Blackwell)
typedef unsigned long long ull_t;
__device__ __forceinline__ ull_t pack2(float x) {
    ull_t r; asm("mov.b64 %0, {%1, %1};" : "=l"(r) : "f"(x)); return r;
}
__device__ __forceinline__ ull_t fma2(ull_t a, ull_t b, ull_t c) {
    ull_t d; asm("fma.rn.f32x2 %0, %1, %2, %3;" : "=l"(d) : "l"(a), "l"(b), "l"(c));
    return d;
}
__device__ __forceinline__ void unpack2(ull_t v, float& lo, float& hi) {
    asm("mov.b64 {%0, %1}, %2;" : "=f"(lo), "=f"(hi) : "l"(v));
}

// ---------------------------------------------------------------------------
__global__ void init_table_kernel() {
    int t = blockIdx.x * blockDim.x + threadIdx.x;
    if (t <= NLEN) {
        float s, c;
        sincospif((float)t * (1.0f / 4096.0f), &s, &c);
        g_tab[t] = c + s;
    }
}

// -------- Phase A stages 1-4: all twiddles are literals ---------------------
__device__ __forceinline__ void stagesA(float r[16]) {
    #pragma unroll
    for (int e = 0; e < 16; e += 2) {
        float o = r[e + 1]; r[e + 1] = r[e] - o; r[e] += o;
    }
    #pragma unroll
    for (int g = 0; g < 16; g += 4)
        #pragma unroll
        for (int e = g; e < g + 2; e++) {
            float o = r[e + 2]; r[e + 2] = r[e] - o; r[e] += o;
        }
    {
        const float c3[4] = {1.0f, 1.41421356237309515f, 1.0f, 0.0f};
        #pragma unroll
        for (int eb = 0; eb < 4; eb++)
            #pragma unroll
            for (int g = 0; g < 16; g += 8) {
                int e = g + eb;
                float o = c3[eb] * r[e + 4]; r[e + 4] = r[e] - o; r[e] += o;
            }
    }
    {
        const float c4[8] = {1.0f, 1.30656296487637653f, 1.41421356237309515f,
                             1.30656296487637653f, 1.0f, 0.54119610014619701f,
                             0.0f, -0.54119610014619701f};
        #pragma unroll
        for (int e = 0; e < 8; e++) {
            float o = c4[e] * r[e + 8]; r[e + 8] = r[e] - o; r[e] += o;
        }
    }
}

// -------- Phase B stages 5-8: remapped so twiddles are warp-uniform ---------
__device__ __forceinline__ void phaseB(float* sm, float r[16], int t,
                                       const float* __restrict__ tab) {
    const int wid  = t >> 5;
    const int lane = t & 31;
    const int base = (lane << 8) | wid;
    #pragma unroll
    for (int s = 0; s < 16; s++) r[s] = sm[swz(base | (s << 4))];
    {
        float cas = tab[wid << 8];
        #pragma unroll
        for (int s = 0; s < 16; s += 2) {
            float o = cas * r[s + 1]; r[s + 1] = r[s] - o; r[s] += o;
        }
    }
    #pragma unroll
    for (int sb = 0; sb < 2; sb++) {
        float cas = tab[((sb << 4) | wid) << 7];
        #pragma unroll
        for (int g = 0; g < 16; g += 4) {
            int s = g + sb;
            float o = cas * r[s + 2]; r[s + 2] = r[s] - o; r[s] += o;
        }
    }
    #pragma unroll
    for (int sb = 0; sb < 4; sb++) {
        float cas = tab[((sb << 4) | wid) << 6];
        #pragma unroll
        for (int g = 0; g < 16; g += 8) {
            int s = g + sb;
            float o = cas * r[s + 4]; r[s + 4] = r[s] - o; r[s] += o;
        }
    }
    #pragma unroll
    for (int s = 0; s < 8; s++) {
        float cas = tab[((s << 4) | wid) << 5];
        float o = cas * r[s + 8]; r[s + 8] = r[s] - o; r[s] += o;
    }
    #pragma unroll
    for (int s = 0; s < 16; s++) sm[swz(base | (s << 4))] = r[s];
}

// -------- forward: x[row][0..8192) -> xm[row][0..1024) ----------------------
// Strided coalesced load + register bit-reversal: stages 1-4 run off the
// global load with ZERO smem round-trips (thread t owns u-block 16*rev9(t)).
__global__ __launch_bounds__(512, 2) void fht_fwd_kernel(const float* __restrict__ x) {
    __shared__ float sm[NLEN];
    const int row = blockIdx.x;
    const int t = threadIdx.x;
    const float* __restrict__ tab = g_tab;
    const float* __restrict__ xr = x + (size_t)row * NLEN;

    float r[16];
    {
        // r[rev4(e)] = x[e*512 + t]  (each load coalesced across the warp)
        const int REV4[16] = {0,8,4,12, 2,10,6,14, 1,9,5,13, 3,11,7,15};
        #pragma unroll
        for (int e = 0; e < 16; e++) r[REV4[e]] = xr[e * 512 + t];
        stagesA(r);
        const int ub = rev9(t) << 4;
        #pragma unroll
        for (int e = 0; e < 16; e++) sm[swz(ub | e)] = r[e];
    }
    __syncthreads();

    phaseB(sm, r, t, tab);
    __syncthreads();

    {
        const int low8 = t & 255;
        const int base = ((t >> 8) << 12) | low8;
        float c9   = tab[low8 << 4];
        float c10p = tab[low8 << 3], c10m = tab[8192 - (low8 << 3)];
        float c11p = tab[low8 << 2], c11m = tab[8192 - (low8 << 2)];
        float c12p = tab[low8 << 1], c12m = tab[8192 - (low8 << 1)];
        #pragma unroll
        for (int s = 0; s < 16; s++) r[s] = sm[swz(base | (s << 8))];
        #pragma unroll
        for (int s = 0; s < 16; s += 2) {
            float o = c9 * r[s + 1]; r[s + 1] = r[s] - o; r[s] += o;
        }
        #pragma unroll
        for (int g = 0; g < 16; g += 4) {
            float o0 = c10p * r[g + 2]; r[g + 2] = r[g]     - o0; r[g]     += o0;
            float o1 = c10m * r[g + 3]; r[g + 3] = r[g + 1] - o1; r[g + 1] += o1;
        }
        {
            const float w11[4] = { c11p, RSQ2 * (c11p + c11m), c11m, RSQ2 * (c11m - c11p) };
            #pragma unroll
            for (int sb = 0; sb < 4; sb++) {
                r[sb]     += w11[sb] * r[sb + 4];
                r[sb + 8] += w11[sb] * r[sb + 12];
            }
        }
        {
            r[0] += c12p * r[8];
            r[1] += (C8L * c12p + S8L * c12m) * r[9];
            r[2] += (RSQ2 * (c12p + c12m))    * r[10];
            r[3] += (S8L * c12p + C8L * c12m) * r[11];
        }
        #pragma unroll
        for (int s = 0; s < 4; s++) sm[swz(base | (s << 8))] = r[s];
    }
    __syncthreads();

    {
        float* __restrict__ xmr = g_xm + (size_t)row * MODES;
        const int m0 = 2 * t;
        float2 tw = *(const float2*)&tab[m0];
        float e0 = sm[swz(m0)],     o0 = sm[swz(m0 + 4096)];
        float e1 = sm[swz(m0 + 1)], o1 = sm[swz(m0 + 1 + 4096)];
        float2 res;
        res.x = e0 + tw.x * o0;
        res.y = e1 + tw.y * o1;
        *(float2*)&xmr[m0] = res;
    }
}

// -------- inverse: z[row][0..1024) zero-padded -> out[row][0..8192)/8192 ----
__global__ __launch_bounds__(512, 2) void fht_inv_kernel(float* __restrict__ out) {
    __shared__ float sm[NLEN];
    const int row = blockIdx.x;
    const int t = threadIdx.x;
    const float* __restrict__ tab = g_tab;
    const float* __restrict__ zr = g_z + (size_t)row * MODES;

    {
        float v0 = zr[t];
        float v1 = zr[t + 512];
        const int ub = rev9(t) << 4;
        const float c4[8] = {1.0f, 1.30656296487637653f, 1.41421356237309515f,
                             1.30656296487637653f, 1.0f, 0.54119610014619701f,
                             0.0f, -0.54119610014619701f};
        #pragma unroll
        for (int e = 0; e < 8; e++) {
            float o = c4[e] * v1;
            sm[swz(ub | e)]       = v0 + o;
            sm[swz(ub | (e + 8))] = v0 - o;
        }
    }
    __syncthreads();

    float r[16];
    phaseB(sm, r, t, tab);
    __syncthreads();

    {
        const int low8 = t & 255;
        const int base = ((t >> 8) << 12) | low8;
        float c9   = tab[low8 << 4];
        float c10p = tab[low8 << 3], c10m = tab[8192 - (low8 << 3)];
        float c11p = tab[low8 << 2], c11m = tab[8192 - (low8 << 2)];
        float c12p = tab[low8 << 1], c12m = tab[8192 - (low8 << 1)];
        #pragma unroll
        for (int s = 0; s < 16; s++) r[s] = sm[swz(base | (s << 8))];
        #pragma unroll
        for (int s = 0; s < 16; s += 2) {
            float o = c9 * r[s + 1]; r[s + 1] = r[s] - o; r[s] += o;
        }
        #pragma unroll
        for (int g = 0; g < 16; g += 4) {
            float o0 = c10p * r[g + 2]; r[g + 2] = r[g]     - o0; r[g]     += o0;
            float o1 = c10m * r[g + 3]; r[g + 3] = r[g + 1] - o1; r[g + 1] += o1;
        }
        {
            const float w11[4] = { c11p, RSQ2 * (c11p + c11m), c11m, RSQ2 * (c11m - c11p) };
            #pragma unroll
            for (int sb = 0; sb < 4; sb++) {
                float o0 = w11[sb] * r[sb + 4];  r[sb + 4]  = r[sb]     - o0; r[sb]     += o0;
                float o1 = w11[sb] * r[sb + 12]; r[sb + 12] = r[sb + 8] - o1; r[sb + 8] += o1;
            }
        }
        {
            const float w12[8] = {
                c12p,
                C8L * c12p + S8L * c12m,
                RSQ2 * (c12p + c12m),
                S8L * c12p + C8L * c12m,
                c12m,
                -S8L * c12p + C8L * c12m,
                RSQ2 * (c12m - c12p),
                -C8L * c12p + S8L * c12m
            };
            #pragma unroll
            for (int s = 0; s < 8; s++) {
                float o = w12[s] * r[s + 8]; r[s + 8] = r[s] - o; r[s] += o;
            }
        }
        #pragma unroll
        for (int s = 0; s < 16; s++) sm[swz(base | (s << 8))] = r[s];
    }
    __syncthreads();

    {
        const float scale = 1.0f / (float)NLEN;
        float* __restrict__ orow = out + (size_t)row * NLEN;
        const int k0 = 8 * t;
        float4 tw0 = *(const float4*)&tab[k0];
        float4 tw1 = *(const float4*)&tab[k0 + 4];
        float tws[8] = {tw0.x, tw0.y, tw0.z, tw0.w, tw1.x, tw1.y, tw1.z, tw1.w};
        float lo[8], hi[8];
        #pragma unroll
        for (int q = 0; q < 8; q++) {
            float e = sm[swz(k0 + q)];
            float o = sm[swz(k0 + q + 4096)];
            float tt = tws[q] * o;
            lo[q] = (e + tt) * scale;
            hi[q] = (e - tt) * scale;
        }
        *(float4*)&orow[k0]            = make_float4(lo[0], lo[1], lo[2], lo[3]);
        *(float4*)&orow[k0 + 4]        = make_float4(lo[4], lo[5], lo[6], lo[7]);
        *(float4*)&orow[k0 + 4096]     = make_float4(hi[0], hi[1], hi[2], hi[3]);
        *(float4*)&orow[k0 + 4100]     = make_float4(hi[4], hi[5], hi[6], hi[7]);
    }
}

// -------- generic 32x32 transpose ------------------------------------------
__global__ void transpose_kernel(const float* __restrict__ src,
                                 float* __restrict__ dst, int R, int C) {
    __shared__ float tile[32][33];
    int c0 = blockIdx.x * 32, r0 = blockIdx.y * 32;
    int tx = threadIdx.x, ty = threadIdx.y;
    #pragma unroll
    for (int dy = 0; dy < 32; dy += 8)
        tile[ty + dy][tx] = src[(size_t)(r0 + ty + dy) * C + (c0 + tx)];
    __syncthreads();
    #pragma unroll
    for (int dy = 0; dy < 32; dy += 8)
        dst[(size_t)(c0 + ty + dy) * R + (r0 + tx)] = tile[tx][ty + dy];
}

// -------- paired mode mixing: block m computes z(m) AND z(m') ---------------
// z(m)  = sum_i a*w(m)  + d*w(m')
// z(m') = sum_i a*w(m') - d*w(m)      (a = (x(m)+x(m'))/2, d = (x(m)-x(m'))/2)
__global__ __launch_bounds__(256) void mix_kernel() {
    __shared__ float sa[IROWS];
    __shared__ float sd[IROWS];
    __shared__ float w0[CIN * COUT];
    __shared__ float w1[CIN * COUT];

    const int m  = blockIdx.x;                 // 0..512
    const int mp = (MODES - m) & (MODES - 1);
    const int tid = threadIdx.x;

    const float* xm0 = g_xmT + (size_t)m  * IROWS;
    const float* xm1 = g_xmT + (size_t)mp * IROWS;
    for (int t = tid; t < IROWS; t += 256) {
        float v0 = xm0[t], v1 = xm1[t];
        sa[t] = 0.5f * (v0 + v1);
        sd[t] = 0.5f * (v0 - v1);
    }
    const float* wm0 = g_wT + (size_t)m  * (CIN * COUT);
    const float* wm1 = g_wT + (size_t)mp * (CIN * COUT);
    for (int t = tid; t < CIN * COUT; t += 256) {
        w0[t] = wm0[t];
        w1[t] = wm1[t];
    }
    __syncthreads();

    const int b0 = (tid >> 4) * 2;
    const int o0 = (tid & 15) * 4;

    // Packed accumulators: [b][o-pair]  (pairs (o0,o0+1) and (o0+2,o0+3))
    ull_t A[2][2] = {{0ull, 0ull}, {0ull, 0ull}};
    ull_t B[2][2] = {{0ull, 0ull}, {0ull, 0ull}};

    #pragma unroll 4
    for (int i = 0; i < CIN; i++) {
        float a0 = sa[b0 * CIN + i];
        float a1 = sa[(b0 + 1) * CIN + i];
        float d0 = sd[b0 * CIN + i];
        float d1 = sd[(b0 + 1) * CIN + i];
        ull_t aa0 = pack2(a0), dd0 = pack2(d0), nd0 = pack2(-d0);
        ull_t aa1 = pack2(a1), dd1 = pack2(d1), nd1 = pack2(-d1);
        ull_t w0a = *(const ull_t*)&w0[i * COUT + o0];
        ull_t w0b = *(const ull_t*)&w0[i * COUT + o0 + 2];
        ull_t w1a = *(const ull_t*)&w1[i * COUT + o0];
        ull_t w1b = *(const ull_t*)&w1[i * COUT + o0 + 2];
        A[0][0] = fma2(aa0, w0a, A[0][0]); A[0][0] = fma2(dd0, w1a, A[0][0]);
        A[0][1] = fma2(aa0, w0b, A[0][1]); A[0][1] = fma2(dd0, w1b, A[0][1]);
        A[1][0] = fma2(aa1, w0a, A[1][0]); A[1][0] = fma2(dd1, w1a, A[1][0]);
        A[1][1] = fma2(aa1, w0b, A[1][1]); A[1][1] = fma2(dd1, w1b, A[1][1]);
        B[0][0] = fma2(aa0, w1a, B[0][0]); B[0][0] = fma2(nd0, w0a, B[0][0]);
        B[0][1] = fma2(aa0, w1b, B[0][1]); B[0][1] = fma2(nd0, w0b, B[0][1]);
        B[1][0] = fma2(aa1, w1a, B[1][0]); B[1][0] = fma2(nd1, w0a, B[1][0]);
        B[1][1] = fma2(aa1, w1b, B[1][1]); B[1][1] = fma2(nd1, w0b, B[1][1]);
    }

    float* zr = g_zT + (size_t)m * OROWS;
    #pragma unroll
    for (int bb = 0; bb < 2; bb++) {
        float x0, x1, x2, x3;
        unpack2(A[bb][0], x0, x1);
        unpack2(A[bb][1], x2, x3);
        zr[(b0+bb)*COUT + o0 + 0] = x0; zr[(b0+bb)*COUT + o0 + 1] = x1;
        zr[(b0+bb)*COUT + o0 + 2] = x2; zr[(b0+bb)*COUT + o0 + 3] = x3;
    }
    if (mp != m) {
        float* zp = g_zT + (size_t)mp * OROWS;
        #pragma unroll
        for (int bb = 0; bb < 2; bb++) {
            float x0, x1, x2, x3;
            unpack2(B[bb][0], x0, x1);
            unpack2(B[bb][1], x2, x3);
            zp[(b0+bb)*COUT + o0 + 0] = x0; zp[(b0+bb)*COUT + o0 + 1] = x1;
            zp[(b0+bb)*COUT + o0 + 2] = x2; zp[(b0+bb)*COUT + o0 + 3] = x3;
        }
    }
}

// ---------------------------------------------------------------------------
extern "C" void kernel_launch(void* const* d_in, const int* in_sizes, int n_in,
                              void* d_out, int out_size) {
    const float* x = (const float*)d_in[0];   // [32][64][8192]
    const float* w = (const float*)d_in[1];   // [64][64][1024]
    float* out = (float*)d_out;               // [32][64][8192]

    float* xm  = nullptr; cudaGetSymbolAddress((void**)&xm,  g_xm);
    float* xmT = nullptr; cudaGetSymbolAddress((void**)&xmT, g_xmT);
    float* wT  = nullptr; cudaGetSymbolAddress((void**)&wT,  g_wT);
    float* zT  = nullptr; cudaGetSymbolAddress((void**)&zT,  g_zT);
    float* z   = nullptr; cudaGetSymbolAddress((void**)&z,   g_z);

    init_table_kernel<<<(NLEN + 512) / 512, 512>>>();

    fht_fwd_kernel<<<IROWS, 512>>>(x);

    // xm [2048][1024] -> xmT [1024][2048]
    transpose_kernel<<<dim3(MODES / 32, IROWS / 32), dim3(32, 8)>>>(xm, xmT, IROWS, MODES);
    // w  [4096][1024] -> wT  [1024][4096]
    transpose_kernel<<<dim3(MODES / 32, (CIN * COUT) / 32), dim3(32, 8)>>>(w, wT, CIN * COUT, MODES);

    mix_kernel<<<MODES / 2 + 1, 256>>>();     // 513 blocks: m and m' paired

    // zT [1024][2048] -> z [2048][1024]
    transpose_kernel<<<dim3(OROWS / 32, MODES / 32), dim3(32, 8)>>>(zT, z, MODES, OROWS);

    fht_inv_kernel<<<OROWS, 512>>>(out);
}

// round 7
// speedup vs baseline: 1.3057x; 1.1392x over previous
#include <cuda_runtime.h>
#include <cstdint>

// Problem constants
#define NLEN   8192
#define LOGN   13
#define MODES  1024
#define BATCH  32
#define CIN    64
#define COUT   64
#define IROWS  (BATCH*CIN)    // 2048 input rows
#define OROWS  (BATCH*COUT)   // 2048 output rows

// -------- scratch (no allocations allowed; use __device__ globals) --------
// cas table extended to [0, 8192]: tab[k] = cas(2*pi*k/8192)
__device__ __align__(32) float g_tab[8200];
__device__ __align__(16) float g_xm  [IROWS*MODES];   // [row=b*64+i][m]
__device__ __align__(16) float g_xmT [MODES*IROWS];   // [m][row]
__device__ __align__(16) float g_wT  [MODES*CIN*COUT];// [m][i*64+o]
__device__ __align__(16) float g_zT  [MODES*OROWS];   // [m][b*64+o]
__device__ __align__(16) float g_z   [OROWS*MODES];   // [row=b*64+o][m]

// GF(2)-linear smem swizzle. k0^=u5^u9, k1^=u6^u10, k2^=u7^u11, k3^=u8, k4^=u8^u12.
__device__ __forceinline__ int swz(int u) {
    int f = ((u >> 5) & 7) ^ ((u >> 9) & 7)
          ^ (((u >> 8) & 1) * 0x18)
          ^ (((u >> 12) & 1) * 0x10);
    return u ^ f;
}
__device__ __forceinline__ int rev9(int t) { return (int)(__brev((unsigned)t) >> 23); }

// Literal cas values
#define RSQ2  0.70710678118654752f
#define C8L   0.92387953251128674f
#define S8L   0.38268343236508977f

// Packed f32x2 helpers (Blackwell)
typedef unsigned long long ull_t;
__device__ __forceinline__ ull_t pack2(float x) {
    ull_t r; asm("mov.b64 %0, {%1, %1};" : "=l"(r) : "f"(x)); return r;
}
__device__ __forceinline__ ull_t fma2(ull_t a, ull_t b, ull_t c) {
    ull_t d; asm("fma.rn.f32x2 %0, %1, %2, %3;" : "=l"(d) : "l"(a), "l"(b), "l"(c));
    return d;
}
__device__ __forceinline__ void unpack2(ull_t v, float& lo, float& hi) {
    asm("mov.b64 {%0, %1}, %2;" : "=f"(lo), "=f"(hi) : "l"(v));
}

// ---------------------------------------------------------------------------
__global__ void init_table_kernel() {
    int t = blockIdx.x * blockDim.x + threadIdx.x;
    if (t <= NLEN) {
        float s, c;
        sincospif((float)t * (1.0f / 4096.0f), &s, &c);
        g_tab[t] = c + s;
    }
}

// -------- Phase A stages 1-4: all twiddles are literals ---------------------
__device__ __forceinline__ void stagesA(float r[16]) {
    #pragma unroll
    for (int e = 0; e < 16; e += 2) {
        float o = r[e + 1]; r[e + 1] = r[e] - o; r[e] += o;
    }
    #pragma unroll
    for (int g = 0; g < 16; g += 4)
        #pragma unroll
        for (int e = g; e < g + 2; e++) {
            float o = r[e + 2]; r[e + 2] = r[e] - o; r[e] += o;
        }
    {
        const float c3[4] = {1.0f, 1.41421356237309515f, 1.0f, 0.0f};
        #pragma unroll
        for (int eb = 0; eb < 4; eb++)
            #pragma unroll
            for (int g = 0; g < 16; g += 8) {
                int e = g + eb;
                float o = c3[eb] * r[e + 4]; r[e + 4] = r[e] - o; r[e] += o;
            }
    }
    {
        const float c4[8] = {1.0f, 1.30656296487637653f, 1.41421356237309515f,
                             1.30656296487637653f, 1.0f, 0.54119610014619701f,
                             0.0f, -0.54119610014619701f};
        #pragma unroll
        for (int e = 0; e < 8; e++) {
            float o = c4[e] * r[e + 8]; r[e + 8] = r[e] - o; r[e] += o;
        }
    }
}

// -------- Phase B stages 5-9: twiddles warp-uniform; stage 9 via shfl -------
// u = lane<<8 | s<<4 | wid. Stage 9 partner differs in u-bit 8 = lane bit 0.
__device__ __forceinline__ void phaseB(float* sm, float r[16], int t,
                                       const float* __restrict__ tab) {
    const int wid  = t >> 5;
    const int lane = t & 31;
    const int base = (lane << 8) | wid;
    #pragma unroll
    for (int s = 0; s < 16; s++) r[s] = sm[swz(base | (s << 4))];
    // stage 5: k = wid
    {
        float cas = tab[wid << 8];
        #pragma unroll
        for (int s = 0; s < 16; s += 2) {
            float o = cas * r[s + 1]; r[s + 1] = r[s] - o; r[s] += o;
        }
    }
    // stage 6
    #pragma unroll
    for (int sb = 0; sb < 2; sb++) {
        float cas = tab[((sb << 4) | wid) << 7];
        #pragma unroll
        for (int g = 0; g < 16; g += 4) {
            int s = g + sb;
            float o = cas * r[s + 2]; r[s + 2] = r[s] - o; r[s] += o;
        }
    }
    // stage 7
    #pragma unroll
    for (int sb = 0; sb < 4; sb++) {
        float cas = tab[((sb << 4) | wid) << 6];
        #pragma unroll
        for (int g = 0; g < 16; g += 8) {
            int s = g + sb;
            float o = cas * r[s + 4]; r[s + 4] = r[s] - o; r[s] += o;
        }
    }
    // stage 8
    #pragma unroll
    for (int s = 0; s < 8; s++) {
        float cas = tab[((s << 4) | wid) << 5];
        float o = cas * r[s + 8]; r[s + 8] = r[s] - o; r[s] += o;
    }
    // stage 9: pairs (lane even, lane odd); k = s<<4 | wid (warp-uniform)
    {
        const bool odd = (lane & 1);
        #pragma unroll
        for (int s = 0; s < 16; s++) {
            float cas = tab[(s << 8) | (wid << 4)];
            float p = __shfl_xor_sync(0xFFFFFFFFu, r[s], 1);
            r[s] = odd ? (p - cas * r[s]) : fmaf(cas, p, r[s]);
        }
    }
    #pragma unroll
    for (int s = 0; s < 16; s++) sm[swz(base | (s << 4))] = r[s];
}

// -------- forward: x[row][0..8192) -> xm[row][0..1024) ----------------------
__global__ __launch_bounds__(512, 2) void fht_fwd_kernel(const float* __restrict__ x) {
    __shared__ float sm[NLEN];
    const int row = blockIdx.x;
    const int t = threadIdx.x;
    const float* __restrict__ tab = g_tab;
    const float* __restrict__ xr = x + (size_t)row * NLEN;

    float r[16];
    {
        // r[rev4(e)] = x[e*512 + t]  (each load coalesced across the warp)
        const int REV4[16] = {0,8,4,12, 2,10,6,14, 1,9,5,13, 3,11,7,15};
        #pragma unroll
        for (int e = 0; e < 16; e++) r[REV4[e]] = xr[e * 512 + t];
        stagesA(r);
        const int ub = rev9(t) << 4;
        #pragma unroll
        for (int e = 0; e < 16; e++) sm[swz(ub | e)] = r[e];
    }
    __syncthreads();

    phaseB(sm, r, t, tab);
    __syncthreads();

    // Phase C: u = s<<9 | t; stages 10-13 in registers, 11-13 pruned (m<1024)
    {
        float c10  = tab[t << 3];
        float c11p = tab[t << 2], c11m = tab[8192 - (t << 2)];
        float c12p = tab[t << 1], c12m = tab[8192 - (t << 1)];
        float c13p = tab[t],      c13m = tab[8192 - t];
        #pragma unroll
        for (int s = 0; s < 16; s++) r[s] = sm[swz((s << 9) | t)];
        // stage 10: pairs (s, s+1)
        #pragma unroll
        for (int s = 0; s < 16; s += 2) {
            float o = c10 * r[s + 1]; r[s + 1] = r[s] - o; r[s] += o;
        }
        // stage 11 pruned ('+' branch): pairs (g+sb, g+sb+2)
        {
            const float w11[2] = { c11p, c11m };
            #pragma unroll
            for (int g = 0; g < 16; g += 4)
                #pragma unroll
                for (int sb = 0; sb < 2; sb++)
                    r[g + sb] += w11[sb] * r[g + sb + 2];
        }
        // stage 12 pruned: s in {0,1,8,9}
        {
            const float w12[2] = { c12p, RSQ2 * (c12p + c12m) };
            #pragma unroll
            for (int g = 0; g < 16; g += 8)
                #pragma unroll
                for (int sb = 0; sb < 2; sb++)
                    r[g + sb] += w12[sb] * r[g + sb + 4];
        }
        // stage 13 pruned: s in {0,1}; then m = s<<9 | t
        r[0] += c13p * r[8];
        r[1] += (C8L * c13p + S8L * c13m) * r[9];

        float* __restrict__ xmr = g_xm + (size_t)row * MODES;
        xmr[t]       = r[0];
        xmr[t + 512] = r[1];
    }
}

// -------- inverse: z[row][0..1024) zero-padded -> out[row][0..8192)/8192 ----
__global__ __launch_bounds__(512, 2) void fht_inv_kernel(float* __restrict__ out) {
    __shared__ float sm[NLEN];
    const int row = blockIdx.x;
    const int t = threadIdx.x;
    const float* __restrict__ tab = g_tab;
    const float* __restrict__ zr = g_z + (size_t)row * MODES;

    // stages 1-4 from the two nonzero values (coalesced loads)
    {
        float v0 = zr[t];
        float v1 = zr[t + 512];
        const int ub = rev9(t) << 4;
        const float c4[8] = {1.0f, 1.30656296487637653f, 1.41421356237309515f,
                             1.30656296487637653f, 1.0f, 0.54119610014619701f,
                             0.0f, -0.54119610014619701f};
        #pragma unroll
        for (int e = 0; e < 8; e++) {
            float o = c4[e] * v1;
            sm[swz(ub | e)]       = v0 + o;
            sm[swz(ub | (e + 8))] = v0 - o;
        }
    }
    __syncthreads();

    float r[16];
    phaseB(sm, r, t, tab);
    __syncthreads();

    // Phase C: u = s<<9 | t; stages 10-13 full, in registers; fused output
    {
        float c10  = tab[t << 3];
        float c11p = tab[t << 2], c11m = tab[8192 - (t << 2)];
        float c12p = tab[t << 1], c12m = tab[8192 - (t << 1)];
        float c13p = tab[t],      c13m = tab[8192 - t];
        #pragma unroll
        for (int s = 0; s < 16; s++) r[s] = sm[swz((s << 9) | t)];
        // stage 10
        #pragma unroll
        for (int s = 0; s < 16; s += 2) {
            float o = c10 * r[s + 1]; r[s + 1] = r[s] - o; r[s] += o;
        }
        // stage 11: pairs (g+sb, g+sb+2)
        {
            const float w11[2] = { c11p, c11m };
            #pragma unroll
            for (int g = 0; g < 16; g += 4)
                #pragma unroll
                for (int sb = 0; sb < 2; sb++) {
                    int s = g + sb;
                    float o = w11[sb] * r[s + 2]; r[s + 2] = r[s] - o; r[s] += o;
                }
        }
        // stage 12: pairs (g+sb, g+sb+4)
        {
            const float w12[4] = { c12p, RSQ2 * (c12p + c12m),
                                   c12m, RSQ2 * (c12m - c12p) };
            #pragma unroll
            for (int g = 0; g < 16; g += 8)
                #pragma unroll
                for (int sb = 0; sb < 4; sb++) {
                    int s = g + sb;
                    float o = w12[sb] * r[s + 4]; r[s + 4] = r[s] - o; r[s] += o;
                }
        }
        // stage 13: pairs (s, s+8), cas(th + s*pi/8)
        {
            const float CS[8] = {1.0f, C8L, RSQ2, S8L, 0.0f, -S8L, -RSQ2, -C8L};
            const float SN[8] = {0.0f, S8L, RSQ2, C8L, 1.0f,  C8L,  RSQ2,  S8L};
            #pragma unroll
            for (int s = 0; s < 8; s++) {
                float w13 = CS[s] * c13p + SN[s] * c13m;
                float o = w13 * r[s + 8]; r[s + 8] = r[s] - o; r[s] += o;
            }
        }
        // fused scaled output: out[s<<9 | t] (coalesced per s)
        const float scale = 1.0f / (float)NLEN;
        float* __restrict__ orow = out + (size_t)row * NLEN;
        #pragma unroll
        for (int s = 0; s < 16; s++)
            orow[(s << 9) | t] = r[s] * scale;
    }
}

// -------- float4 32x32 transpose: src[R][C] -> dst[C][R] --------------------
__global__ __launch_bounds__(256) void transpose4_kernel(const float* __restrict__ src,
                                                         float* __restrict__ dst,
                                                         int R, int C) {
    __shared__ float tile[32][33];
    const int c0 = blockIdx.x * 32, r0 = blockIdx.y * 32;
    const int tid = threadIdx.x;
    const int tx = tid & 7, ty = tid >> 3;

    float4 v = *(const float4*)&src[(size_t)(r0 + ty) * C + c0 + 4 * tx];
    tile[ty][4*tx + 0] = v.x;
    tile[ty][4*tx + 1] = v.y;
    tile[ty][4*tx + 2] = v.z;
    tile[ty][4*tx + 3] = v.w;
    __syncthreads();

    float4 o;
    o.x = tile[4*tx + 0][ty];
    o.y = tile[4*tx + 1][ty];
    o.z = tile[4*tx + 2][ty];
    o.w = tile[4*tx + 3][ty];
    *(float4*)&dst[(size_t)(c0 + ty) * R + r0 + 4 * tx] = o;
}

// -------- paired mode mixing: block m computes z(m) AND z(m') ---------------
__global__ __launch_bounds__(256) void mix_kernel() {
    __shared__ float sa[IROWS];
    __shared__ float sd[IROWS];
    __shared__ float w0[CIN * COUT];
    __shared__ float w1[CIN * COUT];

    const int m  = blockIdx.x;                 // 0..512
    const int mp = (MODES - m) & (MODES - 1);
    const int tid = threadIdx.x;

    const float* xm0 = g_xmT + (size_t)m  * IROWS;
    const float* xm1 = g_xmT + (size_t)mp * IROWS;
    for (int t = tid; t < IROWS; t += 256) {
        float v0 = xm0[t], v1 = xm1[t];
        sa[t] = 0.5f * (v0 + v1);
        sd[t] = 0.5f * (v0 - v1);
    }
    const float* wm0 = g_wT + (size_t)m  * (CIN * COUT);
    const float* wm1 = g_wT + (size_t)mp * (CIN * COUT);
    for (int t = tid; t < CIN * COUT; t += 256) {
        w0[t] = wm0[t];
        w1[t] = wm1[t];
    }
    __syncthreads();

    const int b0 = (tid >> 4) * 2;
    const int o0 = (tid & 15) * 4;

    ull_t A[2][2] = {{0ull, 0ull}, {0ull, 0ull}};
    ull_t B[2][2] = {{0ull, 0ull}, {0ull, 0ull}};

    #pragma unroll 4
    for (int i = 0; i < CIN; i++) {
        float a0 = sa[b0 * CIN + i];
        float a1 = sa[(b0 + 1) * CIN + i];
        float d0 = sd[b0 * CIN + i];
        float d1 = sd[(b0 + 1) * CIN + i];
        ull_t aa0 = pack2(a0), dd0 = pack2(d0), nd0 = pack2(-d0);
        ull_t aa1 = pack2(a1), dd1 = pack2(d1), nd1 = pack2(-d1);
        ull_t w0a = *(const ull_t*)&w0[i * COUT + o0];
        ull_t w0b = *(const ull_t*)&w0[i * COUT + o0 + 2];
        ull_t w1a = *(const ull_t*)&w1[i * COUT + o0];
        ull_t w1b = *(const ull_t*)&w1[i * COUT + o0 + 2];
        A[0][0] = fma2(aa0, w0a, A[0][0]); A[0][0] = fma2(dd0, w1a, A[0][0]);
        A[0][1] = fma2(aa0, w0b, A[0][1]); A[0][1] = fma2(dd0, w1b, A[0][1]);
        A[1][0] = fma2(aa1, w0a, A[1][0]); A[1][0] = fma2(dd1, w1a, A[1][0]);
        A[1][1] = fma2(aa1, w0b, A[1][1]); A[1][1] = fma2(dd1, w1b, A[1][1]);
        B[0][0] = fma2(aa0, w1a, B[0][0]); B[0][0] = fma2(nd0, w0a, B[0][0]);
        B[0][1] = fma2(aa0, w1b, B[0][1]); B[0][1] = fma2(nd0, w0b, B[0][1]);
        B[1][0] = fma2(aa1, w1a, B[1][0]); B[1][0] = fma2(nd1, w0a, B[1][0]);
        B[1][1] = fma2(aa1, w1b, B[1][1]); B[1][1] = fma2(nd1, w0b, B[1][1]);
    }

    float* zr = g_zT + (size_t)m * OROWS;
    #pragma unroll
    for (int bb = 0; bb < 2; bb++) {
        float x0, x1, x2, x3;
        unpack2(A[bb][0], x0, x1);
        unpack2(A[bb][1], x2, x3);
        zr[(b0+bb)*COUT + o0 + 0] = x0; zr[(b0+bb)*COUT + o0 + 1] = x1;
        zr[(b0+bb)*COUT + o0 + 2] = x2; zr[(b0+bb)*COUT + o0 + 3] = x3;
    }
    if (mp != m) {
        float* zp = g_zT + (size_t)mp * OROWS;
        #pragma unroll
        for (int bb = 0; bb < 2; bb++) {
            float x0, x1, x2, x3;
            unpack2(B[bb][0], x0, x1);
            unpack2(B[bb][1], x2, x3);
            zp[(b0+bb)*COUT + o0 + 0] = x0; zp[(b0+bb)*COUT + o0 + 1] = x1;
            zp[(b0+bb)*COUT + o0 + 2] = x2; zp[(b0+bb)*COUT + o0 + 3] = x3;
        }
    }
}

// ---------------------------------------------------------------------------
extern "C" void kernel_launch(void* const* d_in, const int* in_sizes, int n_in,
                              void* d_out, int out_size) {
    const float* x = (const float*)d_in[0];   // [32][64][8192]
    const float* w = (const float*)d_in[1];   // [64][64][1024]
    float* out = (float*)d_out;               // [32][64][8192]

    float* xm  = nullptr; cudaGetSymbolAddress((void**)&xm,  g_xm);
    float* xmT = nullptr; cudaGetSymbolAddress((void**)&xmT, g_xmT);
    float* wT  = nullptr; cudaGetSymbolAddress((void**)&wT,  g_wT);
    float* zT  = nullptr; cudaGetSymbolAddress((void**)&zT,  g_zT);
    float* z   = nullptr; cudaGetSymbolAddress((void**)&z,   g_z);

    init_table_kernel<<<(NLEN + 512) / 512, 512>>>();

    fht_fwd_kernel<<<IROWS, 512>>>(x);

    // xm [2048][1024] -> xmT [1024][2048]
    transpose4_kernel<<<dim3(MODES / 32, IROWS / 32), 256>>>(xm, xmT, IROWS, MODES);
    // w  [4096][1024] -> wT  [1024][4096]
    transpose4_kernel<<<dim3(MODES / 32, (CIN * COUT) / 32), 256>>>(w, wT, CIN * COUT, MODES);

    mix_kernel<<<MODES / 2 + 1, 256>>>();     // 513 blocks: m and m' paired

    // zT [1024][2048] -> z [2048][1024]
    transpose4_kernel<<<dim3(OROWS / 32, MODES / 32), 256>>>(zT, z, MODES, OROWS);

    fht_inv_kernel<<<OROWS, 512>>>(out);
}

// round 8
// speedup vs baseline: 1.3417x; 1.0276x over previous
#include <cuda_runtime.h>
#include <cstdint>

// Problem constants
#define NLEN   8192
#define LOGN   13
#define MODES  1024
#define BATCH  32
#define CIN    64
#define COUT   64
#define IROWS  (BATCH*CIN)    // 2048 input rows
#define OROWS  (BATCH*COUT)   // 2048 output rows

// -------- scratch (no allocations allowed; use __device__ globals) --------
// cas table [0, 8192]: tab[k] = cas(2*pi*k/8192)  (phase B / stage 9 only)
__device__ __align__(32) float g_tab[8200];
__device__ __align__(16) float g_xm  [IROWS*MODES];   // [row=b*64+i][m]
__device__ __align__(16) float g_xmT [MODES*IROWS];   // [m][row]
__device__ __align__(16) float g_wT  [MODES*CIN*COUT];// [m][i*64+o]
__device__ __align__(16) float g_zT  [MODES*OROWS];   // [m][b*64+o]
__device__ __align__(16) float g_z   [OROWS*MODES];   // [row=b*64+o][m]

// GF(2)-linear smem swizzle. k0^=u5^u9, k1^=u6^u10, k2^=u7^u11, k3^=u8, k4^=u8^u12.
__device__ __forceinline__ int swz(int u) {
    int f = ((u >> 5) & 7) ^ ((u >> 9) & 7)
          ^ (((u >> 8) & 1) * 0x18)
          ^ (((u >> 12) & 1) * 0x10);
    return u ^ f;
}
__device__ __forceinline__ int rev9(int t) { return (int)(__brev((unsigned)t) >> 23); }

// Literal cas values
#define RSQ2  0.70710678118654752f
#define C8L   0.92387953251128674f
#define S8L   0.38268343236508977f
#define THETA0 7.66990393942820615e-4f   // pi/4096

// Packed f32x2 helpers (Blackwell)
typedef unsigned long long ull_t;
__device__ __forceinline__ ull_t pack2(float x) {
    ull_t r; asm("mov.b64 %0, {%1, %1};" : "=l"(r) : "f"(x)); return r;
}
__device__ __forceinline__ ull_t fma2(ull_t a, ull_t b, ull_t c) {
    ull_t d; asm("fma.rn.f32x2 %0, %1, %2, %3;" : "=l"(d) : "l"(a), "l"(b), "l"(c));
    return d;
}
__device__ __forceinline__ void unpack2(ull_t v, float& lo, float& hi) {
    asm("mov.b64 {%0, %1}, %2;" : "=f"(lo), "=f"(hi) : "l"(v));
}

// Phase-C twiddles via MUFU + double-angle (no memory traffic).
// theta = pi*t/4096; outputs cas at theta (13), 2theta (12), 4theta (11), 8theta (10).
struct CTw { float c13p, c13m, c12p, c12m, c11p, c11m, c10; };
__device__ __forceinline__ CTw ctw(int t) {
    float s1, c1;
    __sincosf((float)t * THETA0, &s1, &c1);
    CTw w;
    w.c13p = c1 + s1;  w.c13m = c1 - s1;
    float s2 = 2.0f * s1 * c1, c2 = fmaf(-2.0f * s1, s1, 1.0f);
    w.c12p = c2 + s2;  w.c12m = c2 - s2;
    float s4 = 2.0f * s2 * c2, c4 = fmaf(-2.0f * s2, s2, 1.0f);
    w.c11p = c4 + s4;  w.c11m = c4 - s4;
    float s8 = 2.0f * s4 * c4, c8 = fmaf(-2.0f * s4, s4, 1.0f);
    w.c10  = c8 + s8;
    return w;
}

// ---------------------------------------------------------------------------
__global__ void init_table_kernel() {
    int t = blockIdx.x * blockDim.x + threadIdx.x;
    if (t <= NLEN) {
        float s, c;
        sincospif((float)t * (1.0f / 4096.0f), &s, &c);
        g_tab[t] = c + s;
    }
}

// -------- Phase A stages 1-4: all twiddles are literals ---------------------
__device__ __forceinline__ void stagesA(float r[16]) {
    #pragma unroll
    for (int e = 0; e < 16; e += 2) {
        float o = r[e + 1]; r[e + 1] = r[e] - o; r[e] += o;
    }
    #pragma unroll
    for (int g = 0; g < 16; g += 4)
        #pragma unroll
        for (int e = g; e < g + 2; e++) {
            float o = r[e + 2]; r[e + 2] = r[e] - o; r[e] += o;
        }
    {
        const float c3[4] = {1.0f, 1.41421356237309515f, 1.0f, 0.0f};
        #pragma unroll
        for (int eb = 0; eb < 4; eb++)
            #pragma unroll
            for (int g = 0; g < 16; g += 8) {
                int e = g + eb;
                float o = c3[eb] * r[e + 4]; r[e + 4] = r[e] - o; r[e] += o;
            }
    }
    {
        const float c4[8] = {1.0f, 1.30656296487637653f, 1.41421356237309515f,
                             1.30656296487637653f, 1.0f, 0.54119610014619701f,
                             0.0f, -0.54119610014619701f};
        #pragma unroll
        for (int e = 0; e < 8; e++) {
            float o = c4[e] * r[e + 8]; r[e + 8] = r[e] - o; r[e] += o;
        }
    }
}

// -------- Phase B stages 5-9: twiddles warp-uniform; stage 9 via shfl -------
__device__ __forceinline__ void phaseB(float* sm, float r[16], int t,
                                       const float* __restrict__ tab) {
    const int wid  = t >> 5;
    const int lane = t & 31;
    const int base = (lane << 8) | wid;
    #pragma unroll
    for (int s = 0; s < 16; s++) r[s] = sm[swz(base | (s << 4))];
    {
        float cas = tab[wid << 8];
        #pragma unroll
        for (int s = 0; s < 16; s += 2) {
            float o = cas * r[s + 1]; r[s + 1] = r[s] - o; r[s] += o;
        }
    }
    #pragma unroll
    for (int sb = 0; sb < 2; sb++) {
        float cas = tab[((sb << 4) | wid) << 7];
        #pragma unroll
        for (int g = 0; g < 16; g += 4) {
            int s = g + sb;
            float o = cas * r[s + 2]; r[s + 2] = r[s] - o; r[s] += o;
        }
    }
    #pragma unroll
    for (int sb = 0; sb < 4; sb++) {
        float cas = tab[((sb << 4) | wid) << 6];
        #pragma unroll
        for (int g = 0; g < 16; g += 8) {
            int s = g + sb;
            float o = cas * r[s + 4]; r[s + 4] = r[s] - o; r[s] += o;
        }
    }
    #pragma unroll
    for (int s = 0; s < 8; s++) {
        float cas = tab[((s << 4) | wid) << 5];
        float o = cas * r[s + 8]; r[s + 8] = r[s] - o; r[s] += o;
    }
    // stage 9: pairs (lane even, lane odd); k = s<<4 | wid (warp-uniform)
    {
        const bool odd = (lane & 1);
        #pragma unroll
        for (int s = 0; s < 16; s++) {
            float cas = tab[(s << 8) | (wid << 4)];
            float p = __shfl_xor_sync(0xFFFFFFFFu, r[s], 1);
            r[s] = odd ? (p - cas * r[s]) : fmaf(cas, p, r[s]);
        }
    }
    #pragma unroll
    for (int s = 0; s < 16; s++) sm[swz(base | (s << 4))] = r[s];
}

// -------- forward: x[row][0..8192) -> xm[row][0..1024) ----------------------
__global__ __launch_bounds__(512, 2) void fht_fwd_kernel(const float* __restrict__ x) {
    __shared__ float sm[NLEN];
    const int row = blockIdx.x;
    const int t = threadIdx.x;
    const float* __restrict__ tab = g_tab;
    const float* __restrict__ xr = x + (size_t)row * NLEN;

    float r[16];
    {
        const int REV4[16] = {0,8,4,12, 2,10,6,14, 1,9,5,13, 3,11,7,15};
        #pragma unroll
        for (int e = 0; e < 16; e++) r[REV4[e]] = xr[e * 512 + t];
        stagesA(r);
        const int ub = rev9(t) << 4;
        #pragma unroll
        for (int e = 0; e < 16; e++) sm[swz(ub | e)] = r[e];
    }
    __syncthreads();

    phaseB(sm, r, t, tab);
    __syncthreads();

    // Phase C: u = s<<9 | t; stages 10-13 in registers, 11-13 pruned (m<1024)
    {
        CTw w = ctw(t);
        #pragma unroll
        for (int s = 0; s < 16; s++) r[s] = sm[swz((s << 9) | t)];
        #pragma unroll
        for (int s = 0; s < 16; s += 2) {
            float o = w.c10 * r[s + 1]; r[s + 1] = r[s] - o; r[s] += o;
        }
        {
            const float w11[2] = { w.c11p, w.c11m };
            #pragma unroll
            for (int g = 0; g < 16; g += 4)
                #pragma unroll
                for (int sb = 0; sb < 2; sb++)
                    r[g + sb] += w11[sb] * r[g + sb + 2];
        }
        {
            const float w12[2] = { w.c12p, RSQ2 * (w.c12p + w.c12m) };
            #pragma unroll
            for (int g = 0; g < 16; g += 8)
                #pragma unroll
                for (int sb = 0; sb < 2; sb++)
                    r[g + sb] += w12[sb] * r[g + sb + 4];
        }
        r[0] += w.c13p * r[8];
        r[1] += (C8L * w.c13p + S8L * w.c13m) * r[9];

        float* __restrict__ xmr = g_xm + (size_t)row * MODES;
        xmr[t]       = r[0];
        xmr[t + 512] = r[1];
    }
}

// -------- inverse: z[row][0..1024) zero-padded -> out[row][0..8192)/8192 ----
__global__ __launch_bounds__(512, 2) void fht_inv_kernel(float* __restrict__ out) {
    __shared__ float sm[NLEN];
    const int row = blockIdx.x;
    const int t = threadIdx.x;
    const float* __restrict__ tab = g_tab;
    const float* __restrict__ zr = g_z + (size_t)row * MODES;

    {
        float v0 = zr[t];
        float v1 = zr[t + 512];
        const int ub = rev9(t) << 4;
        const float c4[8] = {1.0f, 1.30656296487637653f, 1.41421356237309515f,
                             1.30656296487637653f, 1.0f, 0.54119610014619701f,
                             0.0f, -0.54119610014619701f};
        #pragma unroll
        for (int e = 0; e < 8; e++) {
            float o = c4[e] * v1;
            sm[swz(ub | e)]       = v0 + o;
            sm[swz(ub | (e + 8))] = v0 - o;
        }
    }
    __syncthreads();

    float r[16];
    phaseB(sm, r, t, tab);
    __syncthreads();

    // Phase C: u = s<<9 | t; stages 10-13 full, in registers; fused output
    {
        CTw w = ctw(t);
        #pragma unroll
        for (int s = 0; s < 16; s++) r[s] = sm[swz((s << 9) | t)];
        #pragma unroll
        for (int s = 0; s < 16; s += 2) {
            float o = w.c10 * r[s + 1]; r[s + 1] = r[s] - o; r[s] += o;
        }
        {
            const float w11[2] = { w.c11p, w.c11m };
            #pragma unroll
            for (int g = 0; g < 16; g += 4)
                #pragma unroll
                for (int sb = 0; sb < 2; sb++) {
                    int s = g + sb;
                    float o = w11[sb] * r[s + 2]; r[s + 2] = r[s] - o; r[s] += o;
                }
        }
        {
            const float w12[4] = { w.c12p, RSQ2 * (w.c12p + w.c12m),
                                   w.c12m, RSQ2 * (w.c12m - w.c12p) };
            #pragma unroll
            for (int g = 0; g < 16; g += 8)
                #pragma unroll
                for (int sb = 0; sb < 4; sb++) {
                    int s = g + sb;
                    float o = w12[sb] * r[s + 4]; r[s + 4] = r[s] - o; r[s] += o;
                }
        }
        {
            const float CS[8] = {1.0f, C8L, RSQ2, S8L, 0.0f, -S8L, -RSQ2, -C8L};
            const float SN[8] = {0.0f, S8L, RSQ2, C8L, 1.0f,  C8L,  RSQ2,  S8L};
            #pragma unroll
            for (int s = 0; s < 8; s++) {
                float w13 = CS[s] * w.c13p + SN[s] * w.c13m;
                float o = w13 * r[s + 8]; r[s + 8] = r[s] - o; r[s] += o;
            }
        }
        const float scale = 1.0f / (float)NLEN;
        float* __restrict__ orow = out + (size_t)row * NLEN;
        #pragma unroll
        for (int s = 0; s < 16; s++)
            orow[(s << 9) | t] = r[s] * scale;
    }
}

// -------- 64x64-tile float4 transpose (MLP=4): src[R][C] -> dst[C][R] -------
__global__ __launch_bounds__(256) void transpose64_kernel(const float* __restrict__ src,
                                                          float* __restrict__ dst,
                                                          int R, int C) {
    __shared__ float tile[64][65];
    const int c0 = blockIdx.x * 64, r0 = blockIdx.y * 64;
    const int tx = threadIdx.x & 15;        // 16 x float4 = 64 cols
    const int ty = threadIdx.x >> 4;        // 16 rows per pass

    #pragma unroll
    for (int s = 0; s < 4; s++) {
        int rr = ty + 16 * s;
        float4 v = *(const float4*)&src[(size_t)(r0 + rr) * C + c0 + 4 * tx];
        tile[rr][4*tx + 0] = v.x;
        tile[rr][4*tx + 1] = v.y;
        tile[rr][4*tx + 2] = v.z;
        tile[rr][4*tx + 3] = v.w;
    }
    __syncthreads();

    #pragma unroll
    for (int s = 0; s < 4; s++) {
        int cc = ty + 16 * s;
        float4 o;
        o.x = tile[4*tx + 0][cc];
        o.y = tile[4*tx + 1][cc];
        o.z = tile[4*tx + 2][cc];
        o.w = tile[4*tx + 3][cc];
        *(float4*)&dst[(size_t)(c0 + cc) * R + r0 + 4 * tx] = o;
    }
}

// -------- paired mode mixing: block m computes z(m) AND z(m') ---------------
__global__ __launch_bounds__(256) void mix_kernel() {
    __shared__ float sa[IROWS];
    __shared__ float sd[IROWS];
    __shared__ float w0[CIN * COUT];
    __shared__ float w1[CIN * COUT];

    const int m  = blockIdx.x;                 // 0..512
    const int mp = (MODES - m) & (MODES - 1);
    const int tid = threadIdx.x;

    const float* xm0 = g_xmT + (size_t)m  * IROWS;
    const float* xm1 = g_xmT + (size_t)mp * IROWS;
    for (int t = tid; t < IROWS; t += 256) {
        float v0 = xm0[t], v1 = xm1[t];
        sa[t] = 0.5f * (v0 + v1);
        sd[t] = 0.5f * (v0 - v1);
    }
    const float* wm0 = g_wT + (size_t)m  * (CIN * COUT);
    const float* wm1 = g_wT + (size_t)mp * (CIN * COUT);
    for (int t = tid; t < CIN * COUT; t += 256) {
        w0[t] = wm0[t];
        w1[t] = wm1[t];
    }
    __syncthreads();

    const int b0 = (tid >> 4) * 2;
    const int o0 = (tid & 15) * 4;

    ull_t A[2][2] = {{0ull, 0ull}, {0ull, 0ull}};
    ull_t B[2][2] = {{0ull, 0ull}, {0ull, 0ull}};

    #pragma unroll 4
    for (int i = 0; i < CIN; i++) {
        float a0 = sa[b0 * CIN + i];
        float a1 = sa[(b0 + 1) * CIN + i];
        float d0 = sd[b0 * CIN + i];
        float d1 = sd[(b0 + 1) * CIN + i];
        ull_t aa0 = pack2(a0), dd0 = pack2(d0), nd0 = pack2(-d0);
        ull_t aa1 = pack2(a1), dd1 = pack2(d1), nd1 = pack2(-d1);
        ull_t w0a = *(const ull_t*)&w0[i * COUT + o0];
        ull_t w0b = *(const ull_t*)&w0[i * COUT + o0 + 2];
        ull_t w1a = *(const ull_t*)&w1[i * COUT + o0];
        ull_t w1b = *(const ull_t*)&w1[i * COUT + o0 + 2];
        A[0][0] = fma2(aa0, w0a, A[0][0]); A[0][0] = fma2(dd0, w1a, A[0][0]);
        A[0][1] = fma2(aa0, w0b, A[0][1]); A[0][1] = fma2(dd0, w1b, A[0][1]);
        A[1][0] = fma2(aa1, w0a, A[1][0]); A[1][0] = fma2(dd1, w1a, A[1][0]);
        A[1][1] = fma2(aa1, w0b, A[1][1]); A[1][1] = fma2(dd1, w1b, A[1][1]);
        B[0][0] = fma2(aa0, w1a, B[0][0]); B[0][0] = fma2(nd0, w0a, B[0][0]);
        B[0][1] = fma2(aa0, w1b, B[0][1]); B[0][1] = fma2(nd0, w0b, B[0][1]);
        B[1][0] = fma2(aa1, w1a, B[1][0]); B[1][0] = fma2(nd1, w0a, B[1][0]);
        B[1][1] = fma2(aa1, w1b, B[1][1]); B[1][1] = fma2(nd1, w0b, B[1][1]);
    }

    float* zr = g_zT + (size_t)m * OROWS;
    #pragma unroll
    for (int bb = 0; bb < 2; bb++) {
        float x0, x1, x2, x3;
        unpack2(A[bb][0], x0, x1);
        unpack2(A[bb][1], x2, x3);
        zr[(b0+bb)*COUT + o0 + 0] = x0; zr[(b0+bb)*COUT + o0 + 1] = x1;
        zr[(b0+bb)*COUT + o0 + 2] = x2; zr[(b0+bb)*COUT + o0 + 3] = x3;
    }
    if (mp != m) {
        float* zp = g_zT + (size_t)mp * OROWS;
        #pragma unroll
        for (int bb = 0; bb < 2; bb++) {
            float x0, x1, x2, x3;
            unpack2(B[bb][0], x0, x1);
            unpack2(B[bb][1], x2, x3);
            zp[(b0+bb)*COUT + o0 + 0] = x0; zp[(b0+bb)*COUT + o0 + 1] = x1;
            zp[(b0+bb)*COUT + o0 + 2] = x2; zp[(b0+bb)*COUT + o0 + 3] = x3;
        }
    }
}

// ---------------------------------------------------------------------------
extern "C" void kernel_launch(void* const* d_in, const int* in_sizes, int n_in,
                              void* d_out, int out_size) {
    const float* x = (const float*)d_in[0];   // [32][64][8192]
    const float* w = (const float*)d_in[1];   // [64][64][1024]
    float* out = (float*)d_out;               // [32][64][8192]

    float* xm  = nullptr; cudaGetSymbolAddress((void**)&xm,  g_xm);
    float* xmT = nullptr; cudaGetSymbolAddress((void**)&xmT, g_xmT);
    float* wT  = nullptr; cudaGetSymbolAddress((void**)&wT,  g_wT);
    float* zT  = nullptr; cudaGetSymbolAddress((void**)&zT,  g_zT);
    float* z   = nullptr; cudaGetSymbolAddress((void**)&z,   g_z);

    init_table_kernel<<<(NLEN + 512) / 512, 512>>>();

    fht_fwd_kernel<<<IROWS, 512>>>(x);

    // xm [2048][1024] -> xmT [1024][2048]
    transpose64_kernel<<<dim3(MODES / 64, IROWS / 64), 256>>>(xm, xmT, IROWS, MODES);
    // w  [4096][1024] -> wT  [1024][4096]
    transpose64_kernel<<<dim3(MODES / 64, (CIN * COUT) / 64), 256>>>(w, wT, CIN * COUT, MODES);

    mix_kernel<<<MODES / 2 + 1, 256>>>();     // 513 blocks: m and m' paired

    // zT [1024][2048] -> z [2048][1024]
    transpose64_kernel<<<dim3(OROWS / 64, MODES / 64), 256>>>(zT, z, MODES, OROWS);

    fht_inv_kernel<<<OROWS, 512>>>(out);
}